// round 3
// baseline (speedup 1.0000x reference)
#include <cuda_runtime.h>
#include <cuda_bf16.h>
#include <math.h>

// Problem constants
#define BATCH 256
#define TT    200
#define DIN   128
#define HH    256
#define OUTD  118
#define G3    768   // 3*H

typedef unsigned long long ull;

// packed fp32x2 FMA: acc = a*b + acc  (per-lane)
#define FMA2(acc, a, b) \
    asm("fma.rn.f32x2 %0, %1, %2, %0;" : "+l"(acc) : "l"(a), "l"(b))
#define PACK2(d, f) \
    asm("mov.b64 %0, {%1, %1};" : "=l"(d) : "f"(f))
#define UNPACK2(lo, hi, v) \
    asm("mov.b64 {%0, %1}, %2;" : "=f"(lo), "=f"(hi) : "l"(v))

// ---------------- scratch (static device globals; no allocation) -------------
__device__ float g_gx[(size_t)BATCH * TT * G3];   // reused for both layers
__device__ float g_hseq[(size_t)BATCH * TT * HH]; // layer hidden sequence
__device__ float g_hA[BATCH * HH];
__device__ float g_hB[BATCH * HH];
__device__ int   g_flags[16];

// ---------------------------------------------------------------------------
// GEMM: C[M][768] = A[M][K] @ W[768][K]^T + bias[768]
// 128x128 tile, 256 threads, 8m x 8j microtile via f32x2 packed FMA.
// ---------------------------------------------------------------------------
__global__ __launch_bounds__(256) void gemm_bias_kernel(
    const float* __restrict__ A, const float* __restrict__ W,
    const float* __restrict__ bias, float* __restrict__ C,
    int M, int K)
{
    __shared__ float sa[8][128];
    __shared__ float sb[8][128];

    const int nb = blockIdx.x * 128;
    const int mb = blockIdx.y * 128;
    const int tid = threadIdx.x;
    const int tx = tid & 15;
    const int ty = tid >> 4;

    const int lrow = tid >> 1;
    const int lseg = (tid & 1) * 4;

    const float* Aptr = A + (size_t)(mb + lrow) * K + lseg;
    const float* Wptr = W + (size_t)(nb + lrow) * K + lseg;

    // 8 rows x 4 packed-col-pairs of fp32x2 accumulators
    ull acc2[8][4];
#pragma unroll
    for (int i = 0; i < 8; i++)
#pragma unroll
        for (int q = 0; q < 4; q++) acc2[i][q] = 0ull;

    float4 av = *(const float4*)(Aptr);
    float4 bv = *(const float4*)(Wptr);

    const int nkt = K >> 3;
    for (int kt = 0; kt < nkt; kt++) {
        __syncthreads();
        sa[lseg + 0][lrow] = av.x; sa[lseg + 1][lrow] = av.y;
        sa[lseg + 2][lrow] = av.z; sa[lseg + 3][lrow] = av.w;
        sb[lseg + 0][lrow] = bv.x; sb[lseg + 1][lrow] = bv.y;
        sb[lseg + 2][lrow] = bv.z; sb[lseg + 3][lrow] = bv.w;
        __syncthreads();
        if (kt + 1 < nkt) {
            av = *(const float4*)(Aptr + (kt + 1) * 8);
            bv = *(const float4*)(Wptr + (kt + 1) * 8);
        }
#pragma unroll
        for (int k = 0; k < 8; k++) {
            float a_[8];
            *(float4*)(a_)     = *(const float4*)&sa[k][ty * 8];
            *(float4*)(a_ + 4) = *(const float4*)&sa[k][ty * 8 + 4];
            const ull* bp = (const ull*)&sb[k][tx * 8];
            const ull bq0 = bp[0], bq1 = bp[1], bq2 = bp[2], bq3 = bp[3];
#pragma unroll
            for (int i = 0; i < 8; i++) {
                ull pa;
                PACK2(pa, a_[i]);
                FMA2(acc2[i][0], pa, bq0);
                FMA2(acc2[i][1], pa, bq1);
                FMA2(acc2[i][2], pa, bq2);
                FMA2(acc2[i][3], pa, bq3);
            }
        }
    }

    float bb[8];
#pragma unroll
    for (int j = 0; j < 8; j++) bb[j] = bias[nb + tx * 8 + j];
#pragma unroll
    for (int i = 0; i < 8; i++) {
        const int row = mb + ty * 8 + i;
        float* cp = C + (size_t)row * G3 + nb + tx * 8;
        float c_[8];
#pragma unroll
        for (int q = 0; q < 4; q++)
            UNPACK2(c_[2 * q], c_[2 * q + 1], acc2[i][q]);
        float4 v0, v1;
        v0.x = c_[0] + bb[0]; v0.y = c_[1] + bb[1];
        v0.z = c_[2] + bb[2]; v0.w = c_[3] + bb[3];
        v1.x = c_[4] + bb[4]; v1.y = c_[5] + bb[5];
        v1.z = c_[6] + bb[6]; v1.w = c_[7] + bb[7];
        *(float4*)(cp)     = v0;
        *(float4*)(cp + 4) = v1;
    }
}

// ---------------------------------------------------------------------------
// Persistent GRU layer kernel (unchanged structure, f32x2 inner loop).
// ---------------------------------------------------------------------------
#define WPAD 34
#define HPAD 18
#define SMEM_FLOATS (3 * 256 * WPAD + 256 * HPAD)

__device__ __forceinline__ float sigm(float x) {
    return __fdividef(1.f, 1.f + __expf(-x));
}
__device__ __forceinline__ float tanh_fast(float x) {
    return 1.f - 2.f * __fdividef(1.f, __expf(2.f * x) + 1.f);
}

__global__ __launch_bounds__(128) void gru_layer_kernel(
    float* __restrict__ hA, float* __restrict__ hB,
    const float* __restrict__ Whh, const float* __restrict__ bhh,
    const float* __restrict__ gx,
    float* __restrict__ hseq,
    int* __restrict__ flags)
{
    extern __shared__ float smem[];
    float* sW = smem;                    // [(g*256+k)*WPAD + j]
    float* sh = smem + 3 * 256 * WPAD;   // [k*HPAD + m]

    const int jt = blockIdx.x;           // 0..7
    const int mt = blockIdx.y;           // 0..15
    const int jb = jt * 32;
    const int mb = mt * 16;
    const int tid = threadIdx.x;
    const int tx = tid & 15;
    const int ty = tid >> 4;
    const int tj = tx * 2;
    const int tm = ty * 2;

    // one-time: Whh tile -> smem
    if (tid < 96) {
        const int g = tid >> 5;
        const int j = tid & 31;
        const float* wrow = Whh + (size_t)(g * HH + jb + j) * HH;
        float* dst = sW + j;
#pragma unroll 4
        for (int k = 0; k < 256; k += 4) {
            float4 v = *(const float4*)(wrow + k);
            dst[(g * 256 + k + 0) * WPAD] = v.x;
            dst[(g * 256 + k + 1) * WPAD] = v.y;
            dst[(g * 256 + k + 2) * WPAD] = v.z;
            dst[(g * 256 + k + 3) * WPAD] = v.w;
        }
    }

    float bbr0 = bhh[jb + tj],          bbr1 = bhh[jb + tj + 1];
    float bbz0 = bhh[HH + jb + tj],     bbz1 = bhh[HH + jb + tj + 1];
    float bbn0 = bhh[2 * HH + jb + tj], bbn1 = bhh[2 * HH + jb + tj + 1];

    const int sm_ = tid & 15;
    const int skb = (tid >> 4) * 32;

    const int b0 = mb + tm;
    const int b1 = mb + tm + 1;
    const float* gx0 = gx + (size_t)b0 * TT * G3;
    const float* gx1 = gx + (size_t)b1 * TT * G3;

    __syncthreads();

    for (int t = 0; t < TT; t++) {
        const float* rb = (t & 1) ? hB : hA;
        float*       wb = (t & 1) ? hA : hB;

        if (t > 0) {
            if (tid == 0) {
                const int tgt = 8 * t;
                const volatile int* f = flags + mt;
                while (*f < tgt) { }
            }
            __syncthreads();
        }

        // prefetch gx for this step
        const float* p0 = gx0 + (size_t)t * G3;
        const float* p1 = gx1 + (size_t)t * G3;
        const float gr00 = __ldg(p0 + jb + tj),        gr01 = __ldg(p0 + jb + tj + 1);
        const float gz00 = __ldg(p0 + HH + jb + tj),   gz01 = __ldg(p0 + HH + jb + tj + 1);
        const float gn00 = __ldg(p0 + 2*HH + jb + tj), gn01 = __ldg(p0 + 2*HH + jb + tj + 1);
        const float gr10 = __ldg(p1 + jb + tj),        gr11 = __ldg(p1 + jb + tj + 1);
        const float gz10 = __ldg(p1 + HH + jb + tj),   gz11 = __ldg(p1 + HH + jb + tj + 1);
        const float gn10 = __ldg(p1 + 2*HH + jb + tj), gn11 = __ldg(p1 + 2*HH + jb + tj + 1);

        // stage h tile [k=256][m=16]
        {
            const float* src = rb + (size_t)(mb + sm_) * HH + skb;
#pragma unroll
            for (int i = 0; i < 32; i += 4) {
                float4 v;
                v.x = __ldcg(src + i);
                v.y = __ldcg(src + i + 1);
                v.z = __ldcg(src + i + 2);
                v.w = __ldcg(src + i + 3);
                sh[(skb + i + 0) * HPAD + sm_] = v.x;
                sh[(skb + i + 1) * HPAD + sm_] = v.y;
                sh[(skb + i + 2) * HPAD + sm_] = v.z;
                sh[(skb + i + 3) * HPAD + sm_] = v.w;
            }
        }
        __syncthreads();

        // ---- GEMM from smem: 6 packed accumulators (2m x (2j packed) x 3g) ----
        ull ar0 = 0ull, ar1 = 0ull, az0 = 0ull, az1 = 0ull, an0 = 0ull, an1 = 0ull;

        const float* shp = sh + tm;
        const float* wr_ = sW + tj;
        const float* wz_ = sW + 256 * WPAD + tj;
        const float* wn_ = sW + 512 * WPAD + tj;

#pragma unroll 8
        for (int k = 0; k < 256; k++) {
            const float2 hv = *(const float2*)(shp + k * HPAD);
            const ull wr = *(const ull*)(wr_ + (size_t)k * WPAD);
            const ull wz = *(const ull*)(wz_ + (size_t)k * WPAD);
            const ull wn = *(const ull*)(wn_ + (size_t)k * WPAD);
            ull h0p, h1p;
            PACK2(h0p, hv.x);
            PACK2(h1p, hv.y);
            FMA2(ar0, h0p, wr); FMA2(ar1, h1p, wr);
            FMA2(az0, h0p, wz); FMA2(az1, h1p, wz);
            FMA2(an0, h0p, wn); FMA2(an1, h1p, wn);
        }

        float ar00, ar01, ar10, ar11, az00, az01, az10, az11, an00, an01, an10, an11;
        UNPACK2(ar00, ar01, ar0); UNPACK2(ar10, ar11, ar1);
        UNPACK2(az00, az01, az0); UNPACK2(az10, az11, az1);
        UNPACK2(an00, an01, an0); UNPACK2(an10, an11, an1);

        // ---- gates + h update ----
        const int j0 = jb + tj, j1 = jb + tj + 1;
        const float ho00 = sh[j0 * HPAD + tm],     ho01 = sh[j1 * HPAD + tm];
        const float ho10 = sh[j0 * HPAD + tm + 1], ho11 = sh[j1 * HPAD + tm + 1];

        const float r00 = sigm(gr00 + ar00 + bbr0);
        const float r01 = sigm(gr01 + ar01 + bbr1);
        const float r10 = sigm(gr10 + ar10 + bbr0);
        const float r11 = sigm(gr11 + ar11 + bbr1);
        const float z00 = sigm(gz00 + az00 + bbz0);
        const float z01 = sigm(gz01 + az01 + bbz1);
        const float z10 = sigm(gz10 + az10 + bbz0);
        const float z11 = sigm(gz11 + az11 + bbz1);
        const float n00 = tanh_fast(gn00 + r00 * (an00 + bbn0));
        const float n01 = tanh_fast(gn01 + r01 * (an01 + bbn1));
        const float n10 = tanh_fast(gn10 + r10 * (an10 + bbn0));
        const float n11 = tanh_fast(gn11 + r11 * (an11 + bbn1));

        const float h00 = (1.f - z00) * n00 + z00 * ho00;
        const float h01 = (1.f - z01) * n01 + z01 * ho01;
        const float h10 = (1.f - z10) * n10 + z10 * ho10;
        const float h11 = (1.f - z11) * n11 + z11 * ho11;

        __stcg(wb + (size_t)b0 * HH + j0, h00);
        __stcg(wb + (size_t)b0 * HH + j1, h01);
        __stcg(wb + (size_t)b1 * HH + j0, h10);
        __stcg(wb + (size_t)b1 * HH + j1, h11);

        float* hs0 = hseq + ((size_t)b0 * TT + t) * HH;
        float* hs1 = hseq + ((size_t)b1 * TT + t) * HH;
        hs0[j0] = h00; hs0[j1] = h01;
        hs1[j0] = h10; hs1[j1] = h11;

        __threadfence();
        __syncthreads();
        if (tid == 0) atomicAdd(flags + mt, 1);
    }
}

// ---------------------------------------------------------------------------
// Final FC
// ---------------------------------------------------------------------------
__global__ __launch_bounds__(128) void fc_kernel(
    const float* __restrict__ hseq, const float* __restrict__ W,
    const float* __restrict__ bias, float* __restrict__ out)
{
    __shared__ float hs[HH];
    const int b = blockIdx.x;
    const float* hrow = hseq + ((size_t)b * TT + (TT - 1)) * HH;
    for (int i = threadIdx.x; i < HH; i += 128) hs[i] = hrow[i];
    __syncthreads();
    const int o = threadIdx.x;
    if (o < OUTD) {
        float acc = bias[o];
        const float* wr = W + (size_t)o * HH;
#pragma unroll 8
        for (int k = 0; k < HH; k++) acc += hs[k] * wr[k];
        out[(size_t)b * OUTD + o] = acc;
    }
}

// ---------------------------------------------------------------------------
extern "C" void kernel_launch(void* const* d_in, const int* in_sizes, int n_in,
                              void* d_out, int out_size)
{
    const float* x    = (const float*)d_in[0];
    const float* Wih0 = (const float*)d_in[1];
    const float* Whh0 = (const float*)d_in[2];
    const float* bih0 = (const float*)d_in[3];
    const float* bhh0 = (const float*)d_in[4];
    const float* Wih1 = (const float*)d_in[5];
    const float* Whh1 = (const float*)d_in[6];
    const float* bih1 = (const float*)d_in[7];
    const float* bhh1 = (const float*)d_in[8];
    const float* fcW  = (const float*)d_in[9];
    const float* fcb  = (const float*)d_in[10];
    float* out = (float*)d_out;

    float *gx, *hseq, *hA, *hB;
    int* flags;
    cudaGetSymbolAddress((void**)&gx, g_gx);
    cudaGetSymbolAddress((void**)&hseq, g_hseq);
    cudaGetSymbolAddress((void**)&hA, g_hA);
    cudaGetSymbolAddress((void**)&hB, g_hB);
    cudaGetSymbolAddress((void**)&flags, g_flags);

    static bool attr_set = false;
    if (!attr_set) {
        cudaFuncSetAttribute(gru_layer_kernel,
                             cudaFuncAttributeMaxDynamicSharedMemorySize,
                             SMEM_FLOATS * (int)sizeof(float));
        attr_set = true;
    }

    const dim3 gemmGrid(G3 / 128, (BATCH * TT) / 128);
    const dim3 layerGrid(8, 16);
    const int smemB = SMEM_FLOATS * (int)sizeof(float);

    // ---- layer 0 ----
    gemm_bias_kernel<<<gemmGrid, 256>>>(x, Wih0, bih0, gx, BATCH * TT, DIN);
    cudaMemsetAsync(hA, 0, BATCH * HH * sizeof(float));
    cudaMemsetAsync(flags, 0, 16 * sizeof(int));
    gru_layer_kernel<<<layerGrid, 128, smemB>>>(hA, hB, Whh0, bhh0, gx, hseq, flags);

    // ---- layer 1 ----
    gemm_bias_kernel<<<gemmGrid, 256>>>(hseq, Wih1, bih1, gx, BATCH * TT, HH);
    cudaMemsetAsync(hA, 0, BATCH * HH * sizeof(float));
    cudaMemsetAsync(flags, 0, 16 * sizeof(int));
    gru_layer_kernel<<<layerGrid, 128, smemB>>>(hA, hB, Whh1, bhh1, gx, hseq, flags);

    // ---- final FC ----
    fc_kernel<<<BATCH, 128>>>(hseq, fcW, fcb, out);
}

// round 4
// speedup vs baseline: 1.1259x; 1.1259x over previous
#include <cuda_runtime.h>
#include <cuda_bf16.h>
#include <math.h>

// Problem constants
#define BATCH 256
#define TT    200
#define DIN   128
#define HH    256
#define OUTD  118
#define G3    768   // 3*H

typedef unsigned long long ull;
typedef unsigned int uint;

// packed fp32x2 FMA helpers (recurrence kernel)
#define FMA2(acc, a, b) \
    asm("fma.rn.f32x2 %0, %1, %2, %0;" : "+l"(acc) : "l"(a), "l"(b))
#define PACK2(d, f) \
    asm("mov.b64 %0, {%1, %1};" : "=l"(d) : "f"(f))
#define UNPACK2(lo, hi, v) \
    asm("mov.b64 {%0, %1}, %2;" : "=f"(lo), "=f"(hi) : "l"(v))

__device__ __forceinline__ uint f2tf32(float f) {
    uint u;
    asm("cvt.rna.tf32.f32 %0, %1;" : "=r"(u) : "f"(f));
    return u;
}

// ---------------- scratch (static device globals; no allocation) -------------
__device__ float g_gx[(size_t)BATCH * TT * G3];
__device__ float g_hseq[(size_t)BATCH * TT * HH];
__device__ float g_hA[BATCH * HH];
__device__ float g_hB[BATCH * HH];
__device__ int   g_flags[16];

// ---------------------------------------------------------------------------
// tf32 tensor-core GEMM: C[M][768] = A[M][K] @ W[768][K]^T + bias
// CTA 128x128, 8 warps (2x4), warp tile 64x32, BK=32, double-buffered smem.
// Smem layout with XOR swizzle: addr(m,k) = m*32 + (((k>>2)^(m&7))<<2) + (k&3)
// -> all fragment LDS.32 conflict-free; global->smem stores are STS.128.
// ---------------------------------------------------------------------------
__global__ __launch_bounds__(256) void gemm_tf32_kernel(
    const float* __restrict__ A, const float* __restrict__ W,
    const float* __restrict__ bias, float* __restrict__ C,
    int M, int K)
{
    extern __shared__ uint smemU[];
    // stage s: A at s*8192, B at s*8192+4096 (uints)
    const int nb = blockIdx.x * 128;
    const int mb = blockIdx.y * 128;
    const int tid = threadIdx.x;
    const int wid = tid >> 5;
    const int lane = tid & 31;
    const int wm = wid & 1;          // 0..1  (64-row slabs)
    const int wn = wid >> 1;         // 0..3  (32-col slabs)
    const int r = lane >> 2;         // 0..7
    const int c = lane & 3;          // 0..3

    // loader mapping: 4 float4 per thread per tile
    const int lm = tid >> 3;               // row for j=0 chunk (i = tid)
    // general: i = tid + j*256 -> m = i>>3, k4 = (i&7)*4
    const float* gA = A + (size_t)mb * K;
    const float* gW = W + (size_t)nb * K;

    float acc[4][4][4];
#pragma unroll
    for (int i = 0; i < 4; i++)
#pragma unroll
        for (int j = 0; j < 4; j++)
#pragma unroll
            for (int q = 0; q < 4; q++) acc[i][j][q] = 0.f;

    const int nk = K >> 5;

    // prefetch chunk 0 into regs
    float4 pa[4], pb[4];
#pragma unroll
    for (int j = 0; j < 4; j++) {
        const int i = tid + j * 256;
        const int m = i >> 3;
        const int k4 = (i & 7) << 2;
        pa[j] = *(const float4*)(gA + (size_t)m * K + k4);
        pb[j] = *(const float4*)(gW + (size_t)m * K + k4);
    }

    for (int kc = 0; kc < nk; kc++) {
        uint* sA = smemU + (kc & 1) * 8192;
        uint* sB = sA + 4096;

        // cvt + swizzled store
#pragma unroll
        for (int j = 0; j < 4; j++) {
            const int i = tid + j * 256;
            const int m = i >> 3;
            const int k4 = (i & 7) << 2;
            const int base = m * 32 + ((((k4 >> 2) ^ (m & 7)) << 2));
            uint4 ua, ub;
            ua.x = f2tf32(pa[j].x); ua.y = f2tf32(pa[j].y);
            ua.z = f2tf32(pa[j].z); ua.w = f2tf32(pa[j].w);
            ub.x = f2tf32(pb[j].x); ub.y = f2tf32(pb[j].y);
            ub.z = f2tf32(pb[j].z); ub.w = f2tf32(pb[j].w);
            *(uint4*)(sA + base) = ua;
            *(uint4*)(sB + base) = ub;
        }
        __syncthreads();

        // prefetch next chunk
        if (kc + 1 < nk) {
            const int kb = (kc + 1) << 5;
#pragma unroll
            for (int j = 0; j < 4; j++) {
                const int i = tid + j * 256;
                const int m = i >> 3;
                const int k4 = (i & 7) << 2;
                pa[j] = *(const float4*)(gA + (size_t)m * K + kb + k4);
                pb[j] = *(const float4*)(gW + (size_t)m * K + kb + k4);
            }
        }

        // compute: 4 kf x (4 mf x 4 nf) mma
#pragma unroll
        for (int kf = 0; kf < 4; kf++) {
            const int k0 = kf * 8 + c;       // a0/b0 k
            const int k1 = k0 + 4;           // a2/b1 k
            // B fragments: n = wn*32 + nf*8 + r
            uint b0[4], b1[4];
#pragma unroll
            for (int nf = 0; nf < 4; nf++) {
                const int n = wn * 32 + nf * 8 + r;
                b0[nf] = sB[n * 32 + (((k0 >> 2) ^ (n & 7)) << 2) + (k0 & 3)];
                b1[nf] = sB[n * 32 + (((k1 >> 2) ^ (n & 7)) << 2) + (k1 & 3)];
            }
#pragma unroll
            for (int mf = 0; mf < 4; mf++) {
                const int m0 = wm * 64 + mf * 16 + r;
                const int m1 = m0 + 8;
                const uint a0 = sA[m0 * 32 + (((k0 >> 2) ^ (m0 & 7)) << 2) + (k0 & 3)];
                const uint a1 = sA[m1 * 32 + (((k0 >> 2) ^ (m1 & 7)) << 2) + (k0 & 3)];
                const uint a2 = sA[m0 * 32 + (((k1 >> 2) ^ (m0 & 7)) << 2) + (k1 & 3)];
                const uint a3 = sA[m1 * 32 + (((k1 >> 2) ^ (m1 & 7)) << 2) + (k1 & 3)];
#pragma unroll
                for (int nf = 0; nf < 4; nf++) {
                    asm("mma.sync.aligned.m16n8k8.row.col.f32.tf32.tf32.f32 "
                        "{%0,%1,%2,%3}, {%4,%5,%6,%7}, {%8,%9}, {%0,%1,%2,%3};"
                        : "+f"(acc[mf][nf][0]), "+f"(acc[mf][nf][1]),
                          "+f"(acc[mf][nf][2]), "+f"(acc[mf][nf][3])
                        : "r"(a0), "r"(a1), "r"(a2), "r"(a3),
                          "r"(b0[nf]), "r"(b1[nf]));
                }
            }
        }
        __syncthreads();
    }

    // epilogue: bias + store
#pragma unroll
    for (int nf = 0; nf < 4; nf++) {
        const int n = nb + wn * 32 + nf * 8 + c * 2;
        const float bb0 = bias[n], bb1 = bias[n + 1];
#pragma unroll
        for (int mf = 0; mf < 4; mf++) {
            const int m0 = mb + wm * 64 + mf * 16 + r;
            float2 v0, v1;
            v0.x = acc[mf][nf][0] + bb0; v0.y = acc[mf][nf][1] + bb1;
            v1.x = acc[mf][nf][2] + bb0; v1.y = acc[mf][nf][3] + bb1;
            *(float2*)(C + (size_t)m0 * G3 + n)       = v0;
            *(float2*)(C + (size_t)(m0 + 8) * G3 + n) = v1;
        }
    }
}

// ---------------------------------------------------------------------------
// Persistent GRU layer kernel (unchanged from R2; smem-crossbar bound)
// ---------------------------------------------------------------------------
#define WPAD 34
#define HPAD 18
#define SMEM_FLOATS (3 * 256 * WPAD + 256 * HPAD)

__device__ __forceinline__ float sigm(float x) {
    return __fdividef(1.f, 1.f + __expf(-x));
}
__device__ __forceinline__ float tanh_fast(float x) {
    return 1.f - 2.f * __fdividef(1.f, __expf(2.f * x) + 1.f);
}

__global__ __launch_bounds__(128) void gru_layer_kernel(
    float* __restrict__ hA, float* __restrict__ hB,
    const float* __restrict__ Whh, const float* __restrict__ bhh,
    const float* __restrict__ gx,
    float* __restrict__ hseq,
    int* __restrict__ flags)
{
    extern __shared__ float smem[];
    float* sW = smem;
    float* sh = smem + 3 * 256 * WPAD;

    const int jt = blockIdx.x;
    const int mt = blockIdx.y;
    const int jb = jt * 32;
    const int mb = mt * 16;
    const int tid = threadIdx.x;
    const int tx = tid & 15;
    const int ty = tid >> 4;
    const int tj = tx * 2;
    const int tm = ty * 2;

    if (tid < 96) {
        const int g = tid >> 5;
        const int j = tid & 31;
        const float* wrow = Whh + (size_t)(g * HH + jb + j) * HH;
        float* dst = sW + j;
#pragma unroll 4
        for (int k = 0; k < 256; k += 4) {
            float4 v = *(const float4*)(wrow + k);
            dst[(g * 256 + k + 0) * WPAD] = v.x;
            dst[(g * 256 + k + 1) * WPAD] = v.y;
            dst[(g * 256 + k + 2) * WPAD] = v.z;
            dst[(g * 256 + k + 3) * WPAD] = v.w;
        }
    }

    float bbr0 = bhh[jb + tj],          bbr1 = bhh[jb + tj + 1];
    float bbz0 = bhh[HH + jb + tj],     bbz1 = bhh[HH + jb + tj + 1];
    float bbn0 = bhh[2 * HH + jb + tj], bbn1 = bhh[2 * HH + jb + tj + 1];

    const int sm_ = tid & 15;
    const int skb = (tid >> 4) * 32;

    const int b0 = mb + tm;
    const int b1 = mb + tm + 1;
    const float* gx0 = gx + (size_t)b0 * TT * G3;
    const float* gx1 = gx + (size_t)b1 * TT * G3;

    __syncthreads();

    for (int t = 0; t < TT; t++) {
        const float* rb = (t & 1) ? hB : hA;
        float*       wb = (t & 1) ? hA : hB;

        if (t > 0) {
            if (tid == 0) {
                const int tgt = 8 * t;
                const volatile int* f = flags + mt;
                while (*f < tgt) { }
            }
            __syncthreads();
        }

        const float* p0 = gx0 + (size_t)t * G3;
        const float* p1 = gx1 + (size_t)t * G3;
        const float gr00 = __ldg(p0 + jb + tj),        gr01 = __ldg(p0 + jb + tj + 1);
        const float gz00 = __ldg(p0 + HH + jb + tj),   gz01 = __ldg(p0 + HH + jb + tj + 1);
        const float gn00 = __ldg(p0 + 2*HH + jb + tj), gn01 = __ldg(p0 + 2*HH + jb + tj + 1);
        const float gr10 = __ldg(p1 + jb + tj),        gr11 = __ldg(p1 + jb + tj + 1);
        const float gz10 = __ldg(p1 + HH + jb + tj),   gz11 = __ldg(p1 + HH + jb + tj + 1);
        const float gn10 = __ldg(p1 + 2*HH + jb + tj), gn11 = __ldg(p1 + 2*HH + jb + tj + 1);

        {
            const float* src = rb + (size_t)(mb + sm_) * HH + skb;
#pragma unroll
            for (int i = 0; i < 32; i += 4) {
                float4 v;
                v.x = __ldcg(src + i);
                v.y = __ldcg(src + i + 1);
                v.z = __ldcg(src + i + 2);
                v.w = __ldcg(src + i + 3);
                sh[(skb + i + 0) * HPAD + sm_] = v.x;
                sh[(skb + i + 1) * HPAD + sm_] = v.y;
                sh[(skb + i + 2) * HPAD + sm_] = v.z;
                sh[(skb + i + 3) * HPAD + sm_] = v.w;
            }
        }
        __syncthreads();

        ull ar0 = 0ull, ar1 = 0ull, az0 = 0ull, az1 = 0ull, an0 = 0ull, an1 = 0ull;

        const float* shp = sh + tm;
        const float* wr_ = sW + tj;
        const float* wz_ = sW + 256 * WPAD + tj;
        const float* wn_ = sW + 512 * WPAD + tj;

#pragma unroll 8
        for (int k = 0; k < 256; k++) {
            const float2 hv = *(const float2*)(shp + k * HPAD);
            const ull wr = *(const ull*)(wr_ + (size_t)k * WPAD);
            const ull wz = *(const ull*)(wz_ + (size_t)k * WPAD);
            const ull wn = *(const ull*)(wn_ + (size_t)k * WPAD);
            ull h0p, h1p;
            PACK2(h0p, hv.x);
            PACK2(h1p, hv.y);
            FMA2(ar0, h0p, wr); FMA2(ar1, h1p, wr);
            FMA2(az0, h0p, wz); FMA2(az1, h1p, wz);
            FMA2(an0, h0p, wn); FMA2(an1, h1p, wn);
        }

        float ar00, ar01, ar10, ar11, az00, az01, az10, az11, an00, an01, an10, an11;
        UNPACK2(ar00, ar01, ar0); UNPACK2(ar10, ar11, ar1);
        UNPACK2(az00, az01, az0); UNPACK2(az10, az11, az1);
        UNPACK2(an00, an01, an0); UNPACK2(an10, an11, an1);

        const int j0 = jb + tj, j1 = jb + tj + 1;
        const float ho00 = sh[j0 * HPAD + tm],     ho01 = sh[j1 * HPAD + tm];
        const float ho10 = sh[j0 * HPAD + tm + 1], ho11 = sh[j1 * HPAD + tm + 1];

        const float r00 = sigm(gr00 + ar00 + bbr0);
        const float r01 = sigm(gr01 + ar01 + bbr1);
        const float r10 = sigm(gr10 + ar10 + bbr0);
        const float r11 = sigm(gr11 + ar11 + bbr1);
        const float z00 = sigm(gz00 + az00 + bbz0);
        const float z01 = sigm(gz01 + az01 + bbz1);
        const float z10 = sigm(gz10 + az10 + bbz0);
        const float z11 = sigm(gz11 + az11 + bbz1);
        const float n00 = tanh_fast(gn00 + r00 * (an00 + bbn0));
        const float n01 = tanh_fast(gn01 + r01 * (an01 + bbn1));
        const float n10 = tanh_fast(gn10 + r10 * (an10 + bbn0));
        const float n11 = tanh_fast(gn11 + r11 * (an11 + bbn1));

        const float h00 = (1.f - z00) * n00 + z00 * ho00;
        const float h01 = (1.f - z01) * n01 + z01 * ho01;
        const float h10 = (1.f - z10) * n10 + z10 * ho10;
        const float h11 = (1.f - z11) * n11 + z11 * ho11;

        __stcg(wb + (size_t)b0 * HH + j0, h00);
        __stcg(wb + (size_t)b0 * HH + j1, h01);
        __stcg(wb + (size_t)b1 * HH + j0, h10);
        __stcg(wb + (size_t)b1 * HH + j1, h11);

        float* hs0 = hseq + ((size_t)b0 * TT + t) * HH;
        float* hs1 = hseq + ((size_t)b1 * TT + t) * HH;
        hs0[j0] = h00; hs0[j1] = h01;
        hs1[j0] = h10; hs1[j1] = h11;

        __threadfence();
        __syncthreads();
        if (tid == 0) atomicAdd(flags + mt, 1);
    }
}

// ---------------------------------------------------------------------------
// Final FC
// ---------------------------------------------------------------------------
__global__ __launch_bounds__(128) void fc_kernel(
    const float* __restrict__ hseq, const float* __restrict__ W,
    const float* __restrict__ bias, float* __restrict__ out)
{
    __shared__ float hs[HH];
    const int b = blockIdx.x;
    const float* hrow = hseq + ((size_t)b * TT + (TT - 1)) * HH;
    for (int i = threadIdx.x; i < HH; i += 128) hs[i] = hrow[i];
    __syncthreads();
    const int o = threadIdx.x;
    if (o < OUTD) {
        float acc = bias[o];
        const float* wr = W + (size_t)o * HH;
#pragma unroll 8
        for (int k = 0; k < HH; k++) acc += hs[k] * wr[k];
        out[(size_t)b * OUTD + o] = acc;
    }
}

// ---------------------------------------------------------------------------
extern "C" void kernel_launch(void* const* d_in, const int* in_sizes, int n_in,
                              void* d_out, int out_size)
{
    const float* x    = (const float*)d_in[0];
    const float* Wih0 = (const float*)d_in[1];
    const float* Whh0 = (const float*)d_in[2];
    const float* bih0 = (const float*)d_in[3];
    const float* bhh0 = (const float*)d_in[4];
    const float* Wih1 = (const float*)d_in[5];
    const float* Whh1 = (const float*)d_in[6];
    const float* bih1 = (const float*)d_in[7];
    const float* bhh1 = (const float*)d_in[8];
    const float* fcW  = (const float*)d_in[9];
    const float* fcb  = (const float*)d_in[10];
    float* out = (float*)d_out;

    float *gx, *hseq, *hA, *hB;
    int* flags;
    cudaGetSymbolAddress((void**)&gx, g_gx);
    cudaGetSymbolAddress((void**)&hseq, g_hseq);
    cudaGetSymbolAddress((void**)&hA, g_hA);
    cudaGetSymbolAddress((void**)&hB, g_hB);
    cudaGetSymbolAddress((void**)&flags, g_flags);

    static bool attr_set = false;
    if (!attr_set) {
        cudaFuncSetAttribute(gru_layer_kernel,
                             cudaFuncAttributeMaxDynamicSharedMemorySize,
                             SMEM_FLOATS * (int)sizeof(float));
        cudaFuncSetAttribute(gemm_tf32_kernel,
                             cudaFuncAttributeMaxDynamicSharedMemorySize,
                             64 * 1024);
        attr_set = true;
    }

    const dim3 gemmGrid(G3 / 128, (BATCH * TT) / 128);
    const dim3 layerGrid(8, 16);
    const int layerSmem = SMEM_FLOATS * (int)sizeof(float);
    const int gemmSmem = 64 * 1024;

    // ---- layer 0 ----
    gemm_tf32_kernel<<<gemmGrid, 256, gemmSmem>>>(x, Wih0, bih0, gx, BATCH * TT, DIN);
    cudaMemsetAsync(hA, 0, BATCH * HH * sizeof(float));
    cudaMemsetAsync(flags, 0, 16 * sizeof(int));
    gru_layer_kernel<<<layerGrid, 128, layerSmem>>>(hA, hB, Whh0, bhh0, gx, hseq, flags);

    // ---- layer 1 ----
    gemm_tf32_kernel<<<gemmGrid, 256, gemmSmem>>>(hseq, Wih1, bih1, gx, BATCH * TT, HH);
    cudaMemsetAsync(hA, 0, BATCH * HH * sizeof(float));
    cudaMemsetAsync(flags, 0, 16 * sizeof(int));
    gru_layer_kernel<<<layerGrid, 128, layerSmem>>>(hA, hB, Whh1, bhh1, gx, hseq, flags);

    // ---- final FC ----
    fc_kernel<<<BATCH, 128>>>(hseq, fcW, fcb, out);
}

// round 5
// speedup vs baseline: 1.3345x; 1.1852x over previous
#include <cuda_runtime.h>
#include <cuda_bf16.h>
#include <math.h>

// Problem constants
#define BATCH 256
#define TT    200
#define DIN   128
#define HH    256
#define OUTD  118
#define G3    768   // 3*H

typedef unsigned long long ull;
typedef unsigned int uint;

// packed fp32x2 FMA helpers
#define FMA2(acc, a, b) \
    asm("fma.rn.f32x2 %0, %1, %2, %0;" : "+l"(acc) : "l"(a), "l"(b))
#define PACK2(d, f) \
    asm("mov.b64 %0, {%1, %1};" : "=l"(d) : "f"(f))
#define UNPACK2(lo, hi, v) \
    asm("mov.b64 {%0, %1}, %2;" : "=f"(lo), "=f"(hi) : "l"(v))

__device__ __forceinline__ uint f2tf32(float f) {
    uint u;
    asm("cvt.rna.tf32.f32 %0, %1;" : "=r"(u) : "f"(f));
    return u;
}

// ---------------- scratch (static device globals; no allocation) -------------
__device__ float g_gx[(size_t)BATCH * TT * G3];
__device__ float g_hseq[(size_t)BATCH * TT * HH];
__device__ float g_hA[BATCH * HH];
__device__ float g_hB[BATCH * HH];
__device__ int   g_flags[16];

// ---------------------------------------------------------------------------
// tf32 tensor-core GEMM (unchanged from R4)
// ---------------------------------------------------------------------------
__global__ __launch_bounds__(256) void gemm_tf32_kernel(
    const float* __restrict__ A, const float* __restrict__ W,
    const float* __restrict__ bias, float* __restrict__ C,
    int M, int K)
{
    extern __shared__ uint smemU[];
    const int nb = blockIdx.x * 128;
    const int mb = blockIdx.y * 128;
    const int tid = threadIdx.x;
    const int wid = tid >> 5;
    const int lane = tid & 31;
    const int wm = wid & 1;
    const int wn = wid >> 1;
    const int r = lane >> 2;
    const int c = lane & 3;

    const float* gA = A + (size_t)mb * K;
    const float* gW = W + (size_t)nb * K;

    float acc[4][4][4];
#pragma unroll
    for (int i = 0; i < 4; i++)
#pragma unroll
        for (int j = 0; j < 4; j++)
#pragma unroll
            for (int q = 0; q < 4; q++) acc[i][j][q] = 0.f;

    const int nk = K >> 5;

    float4 pa[4], pb[4];
#pragma unroll
    for (int j = 0; j < 4; j++) {
        const int i = tid + j * 256;
        const int m = i >> 3;
        const int k4 = (i & 7) << 2;
        pa[j] = *(const float4*)(gA + (size_t)m * K + k4);
        pb[j] = *(const float4*)(gW + (size_t)m * K + k4);
    }

    for (int kc = 0; kc < nk; kc++) {
        uint* sA = smemU + (kc & 1) * 8192;
        uint* sB = sA + 4096;

#pragma unroll
        for (int j = 0; j < 4; j++) {
            const int i = tid + j * 256;
            const int m = i >> 3;
            const int k4 = (i & 7) << 2;
            const int base = m * 32 + ((((k4 >> 2) ^ (m & 7)) << 2));
            uint4 ua, ub;
            ua.x = f2tf32(pa[j].x); ua.y = f2tf32(pa[j].y);
            ua.z = f2tf32(pa[j].z); ua.w = f2tf32(pa[j].w);
            ub.x = f2tf32(pb[j].x); ub.y = f2tf32(pb[j].y);
            ub.z = f2tf32(pb[j].z); ub.w = f2tf32(pb[j].w);
            *(uint4*)(sA + base) = ua;
            *(uint4*)(sB + base) = ub;
        }
        __syncthreads();

        if (kc + 1 < nk) {
            const int kb = (kc + 1) << 5;
#pragma unroll
            for (int j = 0; j < 4; j++) {
                const int i = tid + j * 256;
                const int m = i >> 3;
                const int k4 = (i & 7) << 2;
                pa[j] = *(const float4*)(gA + (size_t)m * K + kb + k4);
                pb[j] = *(const float4*)(gW + (size_t)m * K + kb + k4);
            }
        }

#pragma unroll
        for (int kf = 0; kf < 4; kf++) {
            const int k0 = kf * 8 + c;
            const int k1 = k0 + 4;
            uint b0[4], b1[4];
#pragma unroll
            for (int nf = 0; nf < 4; nf++) {
                const int n = wn * 32 + nf * 8 + r;
                b0[nf] = sB[n * 32 + (((k0 >> 2) ^ (n & 7)) << 2) + (k0 & 3)];
                b1[nf] = sB[n * 32 + (((k1 >> 2) ^ (n & 7)) << 2) + (k1 & 3)];
            }
#pragma unroll
            for (int mf = 0; mf < 4; mf++) {
                const int m0 = wm * 64 + mf * 16 + r;
                const int m1 = m0 + 8;
                const uint a0 = sA[m0 * 32 + (((k0 >> 2) ^ (m0 & 7)) << 2) + (k0 & 3)];
                const uint a1 = sA[m1 * 32 + (((k0 >> 2) ^ (m1 & 7)) << 2) + (k0 & 3)];
                const uint a2 = sA[m0 * 32 + (((k1 >> 2) ^ (m0 & 7)) << 2) + (k1 & 3)];
                const uint a3 = sA[m1 * 32 + (((k1 >> 2) ^ (m1 & 7)) << 2) + (k1 & 3)];
#pragma unroll
                for (int nf = 0; nf < 4; nf++) {
                    asm("mma.sync.aligned.m16n8k8.row.col.f32.tf32.tf32.f32 "
                        "{%0,%1,%2,%3}, {%4,%5,%6,%7}, {%8,%9}, {%0,%1,%2,%3};"
                        : "+f"(acc[mf][nf][0]), "+f"(acc[mf][nf][1]),
                          "+f"(acc[mf][nf][2]), "+f"(acc[mf][nf][3])
                        : "r"(a0), "r"(a1), "r"(a2), "r"(a3),
                          "r"(b0[nf]), "r"(b1[nf]));
                }
            }
        }
        __syncthreads();
    }

#pragma unroll
    for (int nf = 0; nf < 4; nf++) {
        const int n = nb + wn * 32 + nf * 8 + c * 2;
        const float bb0 = bias[n], bb1 = bias[n + 1];
#pragma unroll
        for (int mf = 0; mf < 4; mf++) {
            const int m0 = mb + wm * 64 + mf * 16 + r;
            float2 v0, v1;
            v0.x = acc[mf][nf][0] + bb0; v0.y = acc[mf][nf][1] + bb1;
            v1.x = acc[mf][nf][2] + bb0; v1.y = acc[mf][nf][3] + bb1;
            *(float2*)(C + (size_t)m0 * G3 + n)       = v0;
            *(float2*)(C + (size_t)(m0 + 8) * G3 + n) = v1;
        }
    }
}

// ---------------------------------------------------------------------------
// Persistent GRU layer kernel, warp-split-K micro-kernel.
// grid (8 jt, 16 mt) = 128 CTAs, 128 threads, 1 CTA/SM.
// Smem: sW [3g][256k][32j] (96KB, no pad: rows 128B), sh [256k][16m] (16KB),
//       sp partials [4w][3g][16m][32j] (24KB).
// Warp w handles K slice [w*64, w*64+64). Lane: mq=lane>>3 (m-quad),
// jq=lane&7 (j-quad). 48 FMAs per 64B of smem per k. Partials reduced
// across warps after the FMA loop; reducing thread owns 4 (m,j) outputs.
// ---------------------------------------------------------------------------
#define SW_FLOATS (3 * 256 * 32)
#define SH_FLOATS (256 * 16)
#define SP_FLOATS (4 * 3 * 16 * 32)
#define LAYER_SMEM_FLOATS (SW_FLOATS + SH_FLOATS + SP_FLOATS)

__device__ __forceinline__ float sigm(float x) {
    return __fdividef(1.f, 1.f + __expf(-x));
}
__device__ __forceinline__ float tanh_fast(float x) {
    return 1.f - 2.f * __fdividef(1.f, __expf(2.f * x) + 1.f);
}

__global__ __launch_bounds__(128) void gru_layer_kernel(
    float* __restrict__ hA, float* __restrict__ hB,
    const float* __restrict__ Whh, const float* __restrict__ bhh,
    const float* __restrict__ gx,
    float* __restrict__ hseq,
    int* __restrict__ flags)
{
    extern __shared__ float smem[];
    float* sW = smem;                       // [(g*256+k)*32 + j]
    float* sh = smem + SW_FLOATS;           // [k*16 + m]
    float* sp = sh + SH_FLOATS;             // [((w*3+g)*16+m)*32 + j]

    const int jt = blockIdx.x;
    const int mt = blockIdx.y;
    const int jb = jt * 32;
    const int mb = mt * 16;
    const int tid = threadIdx.x;
    const int wid = tid >> 5;
    const int lane = tid & 31;

    // FMA-loop lane mapping
    const int mq = (lane >> 3) * 4;         // m-quad base 0,4,8,12
    const int j0 = (lane & 7) * 4;          // j-quad base 0..28
    const int k0 = wid * 64;                // K slice

    // reduction mapping: 4 consecutive j per thread
    const int m_r = tid >> 3;               // 0..15
    const int j_r = (tid & 7) * 4;          // 0..28

    // ---- one-time: load Whh tile into smem [g][k][j] ----
    if (tid < 96) {
        const int g = tid >> 5;
        const int j = tid & 31;
        const float* wrow = Whh + (size_t)(g * HH + jb + j) * HH;
        float* dst = sW + (size_t)g * 256 * 32 + j;
#pragma unroll 4
        for (int k = 0; k < 256; k += 4) {
            float4 v = *(const float4*)(wrow + k);
            dst[(k + 0) * 32] = v.x;
            dst[(k + 1) * 32] = v.y;
            dst[(k + 2) * 32] = v.z;
            dst[(k + 3) * 32] = v.w;
        }
    }

    // per-thread bias (reduction mapping)
    const float4 br4 = *(const float4*)(bhh + jb + j_r);
    const float4 bz4 = *(const float4*)(bhh + HH + jb + j_r);
    const float4 bn4 = *(const float4*)(bhh + 2 * HH + jb + j_r);

    // h-stage loader mapping
    const int sm_ = tid & 15;
    const int skb = (tid >> 4) * 32;

    // gx pointer for this thread's reduction row
    const int b_r = mb + m_r;
    const float* gxb = gx + (size_t)b_r * TT * G3;

    __syncthreads();

    for (int t = 0; t < TT; t++) {
        const float* rb = (t & 1) ? hB : hA;
        float*       wb = (t & 1) ? hA : hB;

        if (t > 0) {
            if (tid == 0) {
                const int tgt = 8 * t;
                const volatile int* f = flags + mt;
                while (*f < tgt) { }
            }
            __syncthreads();
        }

        // gx for this step (independent of h)
        const float* gxp = gxb + (size_t)t * G3;
        const float4 gr4 = *(const float4*)(gxp + jb + j_r);
        const float4 gz4 = *(const float4*)(gxp + HH + jb + j_r);
        const float4 gn4 = *(const float4*)(gxp + 2 * HH + jb + j_r);

        // stage h tile [k=256][m=16]
        {
            const float* src = rb + (size_t)(mb + sm_) * HH + skb;
#pragma unroll
            for (int i = 0; i < 32; i += 4) {
                float4 v;
                v.x = __ldcg(src + i);
                v.y = __ldcg(src + i + 1);
                v.z = __ldcg(src + i + 2);
                v.w = __ldcg(src + i + 3);
                sh[(skb + i + 0) * 16 + sm_] = v.x;
                sh[(skb + i + 1) * 16 + sm_] = v.y;
                sh[(skb + i + 2) * 16 + sm_] = v.z;
                sh[(skb + i + 3) * 16 + sm_] = v.w;
            }
        }
        __syncthreads();

        // ---- warp-split-K FMA loop: acc[m 0..3][g 0..2][jp 0..1] ----
        ull acc[4][3][2];
#pragma unroll
        for (int m = 0; m < 4; m++)
#pragma unroll
            for (int g = 0; g < 3; g++) {
                acc[m][g][0] = 0ull;
                acc[m][g][1] = 0ull;
            }

        {
            const float* hP = sh + k0 * 16 + mq;
            const float* w0P = sW + (size_t)(0 * 256 + k0) * 32 + j0;
            const float* w1P = sW + (size_t)(1 * 256 + k0) * 32 + j0;
            const float* w2P = sW + (size_t)(2 * 256 + k0) * 32 + j0;
#pragma unroll 4
            for (int kk = 0; kk < 64; kk++) {
                const float4 hq = *(const float4*)(hP + kk * 16);
                ull h0, h1, h2, h3;
                PACK2(h0, hq.x); PACK2(h1, hq.y);
                PACK2(h2, hq.z); PACK2(h3, hq.w);

                const ull* wr = (const ull*)(w0P + (size_t)kk * 32);
                const ull wr0 = wr[0], wr1 = wr[1];
                FMA2(acc[0][0][0], h0, wr0); FMA2(acc[0][0][1], h0, wr1);
                FMA2(acc[1][0][0], h1, wr0); FMA2(acc[1][0][1], h1, wr1);
                FMA2(acc[2][0][0], h2, wr0); FMA2(acc[2][0][1], h2, wr1);
                FMA2(acc[3][0][0], h3, wr0); FMA2(acc[3][0][1], h3, wr1);

                const ull* wz = (const ull*)(w1P + (size_t)kk * 32);
                const ull wz0 = wz[0], wz1 = wz[1];
                FMA2(acc[0][1][0], h0, wz0); FMA2(acc[0][1][1], h0, wz1);
                FMA2(acc[1][1][0], h1, wz0); FMA2(acc[1][1][1], h1, wz1);
                FMA2(acc[2][1][0], h2, wz0); FMA2(acc[2][1][1], h2, wz1);
                FMA2(acc[3][1][0], h3, wz0); FMA2(acc[3][1][1], h3, wz1);

                const ull* wn = (const ull*)(w2P + (size_t)kk * 32);
                const ull wn0 = wn[0], wn1 = wn[1];
                FMA2(acc[0][2][0], h0, wn0); FMA2(acc[0][2][1], h0, wn1);
                FMA2(acc[1][2][0], h1, wn0); FMA2(acc[1][2][1], h1, wn1);
                FMA2(acc[2][2][0], h2, wn0); FMA2(acc[2][2][1], h2, wn1);
                FMA2(acc[3][2][0], h3, wn0); FMA2(acc[3][2][1], h3, wn1);
            }
        }

        // store partials: sp[((w*3+g)*16+m)*32 + j]
#pragma unroll
        for (int m = 0; m < 4; m++) {
#pragma unroll
            for (int g = 0; g < 3; g++) {
                ull* dst = (ull*)(sp + (size_t)(((wid * 3 + g) * 16) + mq + m) * 32 + j0);
                dst[0] = acc[m][g][0];
                dst[1] = acc[m][g][1];
            }
        }
        __syncthreads();

        // ---- reduce across 4 warps + gates; thread owns (m_r, j_r..j_r+3) ----
        float ghr[4], ghz[4], ghn[4];
        {
            float4 s0, s1, s2, s3;
            // gate r
            s0 = *(const float4*)(sp + (size_t)((0 * 3 + 0) * 16 + m_r) * 32 + j_r);
            s1 = *(const float4*)(sp + (size_t)((1 * 3 + 0) * 16 + m_r) * 32 + j_r);
            s2 = *(const float4*)(sp + (size_t)((2 * 3 + 0) * 16 + m_r) * 32 + j_r);
            s3 = *(const float4*)(sp + (size_t)((3 * 3 + 0) * 16 + m_r) * 32 + j_r);
            ghr[0] = (s0.x + s1.x) + (s2.x + s3.x);
            ghr[1] = (s0.y + s1.y) + (s2.y + s3.y);
            ghr[2] = (s0.z + s1.z) + (s2.z + s3.z);
            ghr[3] = (s0.w + s1.w) + (s2.w + s3.w);
            // gate z
            s0 = *(const float4*)(sp + (size_t)((0 * 3 + 1) * 16 + m_r) * 32 + j_r);
            s1 = *(const float4*)(sp + (size_t)((1 * 3 + 1) * 16 + m_r) * 32 + j_r);
            s2 = *(const float4*)(sp + (size_t)((2 * 3 + 1) * 16 + m_r) * 32 + j_r);
            s3 = *(const float4*)(sp + (size_t)((3 * 3 + 1) * 16 + m_r) * 32 + j_r);
            ghz[0] = (s0.x + s1.x) + (s2.x + s3.x);
            ghz[1] = (s0.y + s1.y) + (s2.y + s3.y);
            ghz[2] = (s0.z + s1.z) + (s2.z + s3.z);
            ghz[3] = (s0.w + s1.w) + (s2.w + s3.w);
            // gate n
            s0 = *(const float4*)(sp + (size_t)((0 * 3 + 2) * 16 + m_r) * 32 + j_r);
            s1 = *(const float4*)(sp + (size_t)((1 * 3 + 2) * 16 + m_r) * 32 + j_r);
            s2 = *(const float4*)(sp + (size_t)((2 * 3 + 2) * 16 + m_r) * 32 + j_r);
            s3 = *(const float4*)(sp + (size_t)((3 * 3 + 2) * 16 + m_r) * 32 + j_r);
            ghn[0] = (s0.x + s1.x) + (s2.x + s3.x);
            ghn[1] = (s0.y + s1.y) + (s2.y + s3.y);
            ghn[2] = (s0.z + s1.z) + (s2.z + s3.z);
            ghn[3] = (s0.w + s1.w) + (s2.w + s3.w);
        }

        const float grr[4] = {gr4.x, gr4.y, gr4.z, gr4.w};
        const float gzz[4] = {gz4.x, gz4.y, gz4.z, gz4.w};
        const float gnn[4] = {gn4.x, gn4.y, gn4.z, gn4.w};
        const float brr[4] = {br4.x, br4.y, br4.z, br4.w};
        const float bzz[4] = {bz4.x, bz4.y, bz4.z, bz4.w};
        const float bnn[4] = {bn4.x, bn4.y, bn4.z, bn4.w};

        float hnew[4];
#pragma unroll
        for (int ji = 0; ji < 4; ji++) {
            const float ho = sh[(jb + j_r + ji) * 16 + m_r];
            const float r = sigm(grr[ji] + ghr[ji] + brr[ji]);
            const float z = sigm(gzz[ji] + ghz[ji] + bzz[ji]);
            const float n = tanh_fast(gnn[ji] + r * (ghn[ji] + bnn[ji]));
            hnew[ji] = (1.f - z) * n + z * ho;
        }

        float4 hv4;
        hv4.x = hnew[0]; hv4.y = hnew[1]; hv4.z = hnew[2]; hv4.w = hnew[3];
        // write-through L2 for cross-CTA visibility
        {
            float* dst = wb + (size_t)b_r * HH + jb + j_r;
            asm volatile("st.global.cg.v4.f32 [%0], {%1,%2,%3,%4};"
                         :: "l"(dst), "f"(hv4.x), "f"(hv4.y), "f"(hv4.z), "f"(hv4.w));
        }
        *(float4*)(hseq + ((size_t)b_r * TT + t) * HH + jb + j_r) = hv4;

        __threadfence();
        __syncthreads();
        if (tid == 0) atomicAdd(flags + mt, 1);
    }
}

// ---------------------------------------------------------------------------
// Final FC
// ---------------------------------------------------------------------------
__global__ __launch_bounds__(128) void fc_kernel(
    const float* __restrict__ hseq, const float* __restrict__ W,
    const float* __restrict__ bias, float* __restrict__ out)
{
    __shared__ float hs[HH];
    const int b = blockIdx.x;
    const float* hrow = hseq + ((size_t)b * TT + (TT - 1)) * HH;
    for (int i = threadIdx.x; i < HH; i += 128) hs[i] = hrow[i];
    __syncthreads();
    const int o = threadIdx.x;
    if (o < OUTD) {
        float acc = bias[o];
        const float* wr = W + (size_t)o * HH;
#pragma unroll 8
        for (int k = 0; k < HH; k++) acc += hs[k] * wr[k];
        out[(size_t)b * OUTD + o] = acc;
    }
}

// ---------------------------------------------------------------------------
extern "C" void kernel_launch(void* const* d_in, const int* in_sizes, int n_in,
                              void* d_out, int out_size)
{
    const float* x    = (const float*)d_in[0];
    const float* Wih0 = (const float*)d_in[1];
    const float* Whh0 = (const float*)d_in[2];
    const float* bih0 = (const float*)d_in[3];
    const float* bhh0 = (const float*)d_in[4];
    const float* Wih1 = (const float*)d_in[5];
    const float* Whh1 = (const float*)d_in[6];
    const float* bih1 = (const float*)d_in[7];
    const float* bhh1 = (const float*)d_in[8];
    const float* fcW  = (const float*)d_in[9];
    const float* fcb  = (const float*)d_in[10];
    float* out = (float*)d_out;

    float *gx, *hseq, *hA, *hB;
    int* flags;
    cudaGetSymbolAddress((void**)&gx, g_gx);
    cudaGetSymbolAddress((void**)&hseq, g_hseq);
    cudaGetSymbolAddress((void**)&hA, g_hA);
    cudaGetSymbolAddress((void**)&hB, g_hB);
    cudaGetSymbolAddress((void**)&flags, g_flags);

    static bool attr_set = false;
    if (!attr_set) {
        cudaFuncSetAttribute(gru_layer_kernel,
                             cudaFuncAttributeMaxDynamicSharedMemorySize,
                             LAYER_SMEM_FLOATS * (int)sizeof(float));
        cudaFuncSetAttribute(gemm_tf32_kernel,
                             cudaFuncAttributeMaxDynamicSharedMemorySize,
                             64 * 1024);
        attr_set = true;
    }

    const dim3 gemmGrid(G3 / 128, (BATCH * TT) / 128);
    const dim3 layerGrid(8, 16);
    const int layerSmem = LAYER_SMEM_FLOATS * (int)sizeof(float);
    const int gemmSmem = 64 * 1024;

    // ---- layer 0 ----
    gemm_tf32_kernel<<<gemmGrid, 256, gemmSmem>>>(x, Wih0, bih0, gx, BATCH * TT, DIN);
    cudaMemsetAsync(hA, 0, BATCH * HH * sizeof(float));
    cudaMemsetAsync(flags, 0, 16 * sizeof(int));
    gru_layer_kernel<<<layerGrid, 128, layerSmem>>>(hA, hB, Whh0, bhh0, gx, hseq, flags);

    // ---- layer 1 ----
    gemm_tf32_kernel<<<gemmGrid, 256, gemmSmem>>>(hseq, Wih1, bih1, gx, BATCH * TT, HH);
    cudaMemsetAsync(hA, 0, BATCH * HH * sizeof(float));
    cudaMemsetAsync(flags, 0, 16 * sizeof(int));
    gru_layer_kernel<<<layerGrid, 128, layerSmem>>>(hA, hB, Whh1, bhh1, gx, hseq, flags);

    // ---- final FC ----
    fc_kernel<<<BATCH, 128>>>(hseq, fcW, fcb, out);
}